// round 6
// baseline (speedup 1.0000x reference)
#include <cuda_runtime.h>
#include <cuda_bf16.h>

#define B      512
#define DIM    128
#define MARGIN 0.2f
#define EPSF   1e-6f
#define BIGF   1e30f
#define SENTTH 1e29f
#define FULLM  0xffffffffu

// Scratch state (allocation-free rule). Statics init to zero; the triplet
// kernel's last block resets them after use, so every call leaves them zero.
__device__ float g_D[B * B];
__device__ double g_num = 0.0;
__device__ unsigned long long g_den = 0ull;
__device__ unsigned int g_done = 0u;

// ---------------------------------------------------------------------------
// Kernel 1: pairwise distances via norm expansion (pure-FMA inner loop).
//   u_i = f_i + eps;  D[i,j]^2 = |u_i|^2 + |f_j|^2 - 2 u_i . f_j
// Tile: 32 (i) x 64 (j), 128 blocks = one wave. 256 threads, 2x4 micro-tile.
// ---------------------------------------------------------------------------
#define LD2 130
__global__ __launch_bounds__(256) void dist_kernel(const float* __restrict__ F) {
    extern __shared__ float sm[];
    float* Fi   = sm;                  // 32*130
    float* Fj   = Fi + 32 * LD2;       // 64*130
    float* s_ni = Fj + 64 * LD2;       // 32
    float* s_nj = s_ni + 32;           // 64

    const int tid = threadIdx.x;
    const int tx  = tid & 15;
    const int ty  = tid >> 4;
    const int i0  = blockIdx.y * 32;
    const int j0  = blockIdx.x * 64;

    for (int idx = tid; idx < 96 * DIM; idx += 256) {
        const int r = idx >> 7;
        const int d = idx & 127;
        if (r < 32) Fi[r * LD2 + d] = F[(i0 + r) * DIM + d] + EPSF;
        else        Fj[(r - 32) * LD2 + d] = F[(j0 + r - 32) * DIM + d];
    }
    __syncthreads();

    {
        const int lane = tid & 31;
        const int w    = tid >> 5;
#pragma unroll
        for (int t = 0; t < 12; t++) {
            const int r = w + 8 * t;
            const float* base = (r < 32) ? (Fi + r * LD2) : (Fj + (r - 32) * LD2);
            float s = 0.f;
#pragma unroll
            for (int q = 0; q < 4; q++) {
                const float x = base[lane + 32 * q];
                s = fmaf(x, x, s);
            }
#pragma unroll
            for (int off = 16; off; off >>= 1) s += __shfl_down_sync(FULLM, s, off);
            if (lane == 0) { if (r < 32) s_ni[r] = s; else s_nj[r - 32] = s; }
        }
    }
    __syncthreads();

    float acc[2][4] = {};
#pragma unroll 4
    for (int d = 0; d < DIM; d += 2) {
        const float2 a0 = *(const float2*)&Fi[(ty     ) * LD2 + d];
        const float2 a1 = *(const float2*)&Fi[(ty + 16) * LD2 + d];
        const float2 b0 = *(const float2*)&Fj[(tx     ) * LD2 + d];
        const float2 b1 = *(const float2*)&Fj[(tx + 16) * LD2 + d];
        const float2 b2 = *(const float2*)&Fj[(tx + 32) * LD2 + d];
        const float2 b3 = *(const float2*)&Fj[(tx + 48) * LD2 + d];
        acc[0][0] = fmaf(a0.x, b0.x, fmaf(a0.y, b0.y, acc[0][0]));
        acc[0][1] = fmaf(a0.x, b1.x, fmaf(a0.y, b1.y, acc[0][1]));
        acc[0][2] = fmaf(a0.x, b2.x, fmaf(a0.y, b2.y, acc[0][2]));
        acc[0][3] = fmaf(a0.x, b3.x, fmaf(a0.y, b3.y, acc[0][3]));
        acc[1][0] = fmaf(a1.x, b0.x, fmaf(a1.y, b0.y, acc[1][0]));
        acc[1][1] = fmaf(a1.x, b1.x, fmaf(a1.y, b1.y, acc[1][1]));
        acc[1][2] = fmaf(a1.x, b2.x, fmaf(a1.y, b2.y, acc[1][2]));
        acc[1][3] = fmaf(a1.x, b3.x, fmaf(a1.y, b3.y, acc[1][3]));
    }

#pragma unroll
    for (int r = 0; r < 2; r++) {
        const float ni = s_ni[ty + 16 * r];
        const int   i  = i0 + ty + 16 * r;
#pragma unroll
        for (int c = 0; c < 4; c++) {
            const float d2 = ni + s_nj[tx + 16 * c] - 2.f * acc[r][c];
            g_D[i * B + j0 + tx + 16 * c] = sqrtf(fmaxf(d2, 0.f));
        }
    }
}

// ---------------------------------------------------------------------------
// Kernel 2: triplet reduction. One WARP per anchor row; 512 keys register-
// resident (16/lane, element e = lane*16 + r). Combined pos/neg keys with
// LSB tag: pos -> (d+margin, LSB=1); neg -> (d, LSB=0); diag(excluded) ->
// BIGF (tag 0, but filtered from sums by value guard — R5's absorption bug).
// Register/shfl bitonic sort (no smem, no barriers), then an exclusive scan
// of negative (count, sum) along sorted order gives each positive's
// closed-form contribution: cnt*(d+m) - sum.
// ---------------------------------------------------------------------------
__global__ __launch_bounds__(128) void triplet_kernel(const int* __restrict__ mask,
                                                      float* __restrict__ out) {
    __shared__ float               s_bs[4];
    __shared__ unsigned long long  s_bd[4];

    const int tid  = threadIdx.x;
    const int lane = tid & 31;
    const int warp = tid >> 5;
    const int i    = blockIdx.x * 4 + warp;   // anchor row

    // ---- load + classify into tagged keys -----------------------------------
    float v[16];
    int npos = 0, nneg = 0;
    const float4* Drow = (const float4*)(g_D + i * B);
    const int4*   Mrow = (const int4*)(mask + i * B);

#pragma unroll
    for (int q = 0; q < 4; q++) {
        const float4 d4 = Drow[lane * 4 + q];
        const int4   m4 = Mrow[lane * 4 + q];
        const float dv[4] = {d4.x, d4.y, d4.z, d4.w};
        const int   mv[4] = {m4.x, m4.y, m4.z, m4.w};
#pragma unroll
        for (int t = 0; t < 4; t++) {
            const int j = lane * 16 + q * 4 + t;
            unsigned kb;
            if (mv[t] != 0) {                 // positive (diag included if masked)
                kb = __float_as_uint(dv[t] + MARGIN) | 1u;
                npos++;
            } else if (j == i) {              // excluded diagonal -> sentinel
                kb = __float_as_uint(BIGF) & ~1u;
            } else {                          // negative
                kb = __float_as_uint(dv[t]) & ~1u;
                nneg++;
            }
            v[q * 4 + t] = __uint_as_float(kb);
        }
    }
    const int np = __reduce_add_sync(FULLM, npos);
    const int nn = __reduce_add_sync(FULLM, nneg);

    // ---- bitonic sort of 512 keys, ascending (register + shfl only) ---------
#pragma unroll
    for (int k = 2; k <= 512; k <<= 1) {
        const bool asc_lane_valid = (k >= 16);
        const bool asc_l = ((lane & (k >> 4)) == 0);   // valid when k >= 16
#pragma unroll
        for (int j = k >> 1; j >= 1; j >>= 1) {
            if (j >= 16) {
                const int jl = j >> 4;
                const bool keep_min = (((lane & jl) == 0) == asc_l);
#pragma unroll
                for (int r = 0; r < 16; r++) {
                    const float p = __shfl_xor_sync(FULLM, v[r], jl);
                    v[r] = keep_min ? fminf(v[r], p) : fmaxf(v[r], p);
                }
            } else {
#pragma unroll
                for (int r = 0; r < 16; r++) {
                    if ((r & j) == 0) {
                        const int r2 = r | j;
                        const bool asc = asc_lane_valid ? asc_l : ((r & k) == 0);
                        const float a = v[r], b = v[r2];
                        const float lo = fminf(a, b), hi = fmaxf(a, b);
                        v[r]  = asc ? lo : hi;
                        v[r2] = asc ? hi : lo;
                    }
                }
            }
        }
    }

    // ---- pass 1: per-lane totals of negative (sum, count) -------------------
    // Guard v < SENTTH: the BIGF sentinel must NOT enter the float sum, or it
    // absorbs the real prefix for lane 31 (rs = ls - runs -> 0). R5 bug.
    float runs = 0.f;
    int   runc = 0;
#pragma unroll
    for (int r = 0; r < 16; r++) {
        const bool isneg = ((__float_as_uint(v[r]) & 1u) == 0) && (v[r] < SENTTH);
        if (isneg) { runs += v[r]; runc++; }
    }
    // warp exclusive scan of (runs, runc)
    float ls = runs;
    int   lc = runc;
#pragma unroll
    for (int off = 1; off < 32; off <<= 1) {
        const float y = __shfl_up_sync(FULLM, ls, off);
        const int   z = __shfl_up_sync(FULLM, lc, off);
        if (lane >= off) { ls += y; lc += z; }
    }
    float rs = ls - runs;     // exclusive sum of negatives before this lane
    int   rc = lc - runc;     // exclusive count

    // ---- pass 2: accumulate positive contributions --------------------------
    float local = 0.f;
#pragma unroll
    for (int r = 0; r < 16; r++) {
        const bool ispos = (__float_as_uint(v[r]) & 1u) != 0;
        if (ispos) {
            local += (float)rc * v[r] - rs;
        } else if (v[r] < SENTTH) {
            rs += v[r];
            rc++;
        }
    }

    // ---- warp reduce + block combine + finalize ------------------------------
#pragma unroll
    for (int off = 16; off; off >>= 1)
        local += __shfl_down_sync(FULLM, local, off);

    if (lane == 0) {
        s_bs[warp] = local;
        s_bd[warp] = (unsigned long long)np * (unsigned long long)nn;
    }
    __syncthreads();

    if (tid == 0) {
        float s = s_bs[0] + s_bs[1] + s_bs[2] + s_bs[3];
        unsigned long long d = s_bd[0] + s_bd[1] + s_bd[2] + s_bd[3];
        atomicAdd(&g_num, (double)s);
        atomicAdd(&g_den, d);
        __threadfence();
        const unsigned int ticket = atomicAdd(&g_done, 1u);
        if (ticket == gridDim.x - 1) {
            const double num = atomicAdd(&g_num, 0.0);
            const unsigned long long den = atomicAdd(&g_den, 0ull);
            out[0] = (den > 0ull) ? (float)(num / (double)den) : 0.0f;
            g_num  = 0.0;
            g_den  = 0ull;
            __threadfence();
            g_done = 0u;
        }
    }
}

// ---------------------------------------------------------------------------
extern "C" void kernel_launch(void* const* d_in, const int* in_sizes, int n_in,
                              void* d_out, int out_size) {
    const float* features = (const float*)d_in[0];   // [512,128] f32
    const int*   mask     = (const int*)d_in[1];     // [512,512] i32
    float* out = (float*)d_out;

    const int smem_bytes = (32 * LD2 + 64 * LD2 + 96) * (int)sizeof(float);
    static bool attr_set = false;
    if (!attr_set) {
        cudaFuncSetAttribute(dist_kernel, cudaFuncAttributeMaxDynamicSharedMemorySize,
                             smem_bytes);
        attr_set = true;
    }

    dim3 grid1(B / 64, B / 32);   // 8 x 16 = 128 blocks, single wave
    dist_kernel<<<grid1, 256, smem_bytes>>>(features);
    triplet_kernel<<<B / 4, 128>>>(mask, out);       // warp per row
}